// round 1
// baseline (speedup 1.0000x reference)
#include <cuda_runtime.h>
#include <cuda_bf16.h>

// MorletTransform: per frame f (500 frames), per harmonic k (1..64):
//   T[k] = sum_n  normalizer*gauss[n]*audio[f,n] * exp(-2*pi*i * (f0[f]*k/sr) * n)
//   hd[f,k] = |T[k]| / sum_k |T[k]|;  amp[f] = clip(2*sum_k |T[k]|, 0, 1)
//
// Strategy: fold gauss*normalizer into the frame once (shared mem), then run a
// unit-complex phasor recurrence over n (no per-(n,k) trig), two independent
// even/odd-n chains packed into f32x2 lanes (FFMA2). Reseed the phasor from
// __sincosf every 64 samples to bound recurrence drift (<~6e-6).

#define TWO_PI_F 6.28318530717958647692f

__device__ __forceinline__ unsigned long long fma2(unsigned long long a,
                                                   unsigned long long b,
                                                   unsigned long long c) {
    unsigned long long d;
    asm("fma.rn.f32x2 %0, %1, %2, %3;" : "=l"(d) : "l"(a), "l"(b), "l"(c));
    return d;
}
__device__ __forceinline__ unsigned long long mul2(unsigned long long a,
                                                   unsigned long long b) {
    unsigned long long d;
    asm("mul.rn.f32x2 %0, %1, %2;" : "=l"(d) : "l"(a), "l"(b));
    return d;
}
__device__ __forceinline__ unsigned long long pk(float lo, float hi) {
    unsigned long long d;
    asm("mov.b64 %0, {%1, %2};" : "=l"(d) : "f"(lo), "f"(hi));
    return d;
}
__device__ __forceinline__ void upk(unsigned long long v, float& lo, float& hi) {
    asm("mov.b64 {%0, %1}, %2;" : "=f"(lo), "=f"(hi) : "l"(v));
}

__global__ void __launch_bounds__(256, 4)
morlet_kernel(const float* __restrict__ audio,
              const float* __restrict__ f0,
              float* __restrict__ out_hd,
              float* __restrict__ out_amp) {
    const int f   = blockIdx.x;
    const int tid = threadIdx.x;

    __shared__ __align__(16) float w[1024];
    __shared__ float sRe[256];
    __shared__ float sIm[256];
    __shared__ float sAmp[2];

    // normalizer = 1/sqrt(pi * tp), tp = sr/half_bw = 16000
    const float normalizer = rsqrtf(3.14159265358979f * 16000.0f);
    const float inv_tp     = 1.0f / 16000.0f;

    // --- Load frame, apply Gaussian window, store to shared ---
    {
        float4 a = ((const float4*)(audio))[(size_t)f * 256 + tid];
        int n = tid * 4;
        float d0 = (float)(n + 0 - 512);
        float d1 = (float)(n + 1 - 512);
        float d2 = (float)(n + 2 - 512);
        float d3 = (float)(n + 3 - 512);
        float4 o;
        o.x = a.x * (normalizer * __expf(-d0 * d0 * inv_tp));
        o.y = a.y * (normalizer * __expf(-d1 * d1 * inv_tp));
        o.z = a.z * (normalizer * __expf(-d2 * d2 * inv_tp));
        o.w = a.w * (normalizer * __expf(-d3 * d3 * inv_tp));
        ((float4*)w)[tid] = o;
    }
    __syncthreads();

    // thread -> (harmonic k = (tid&63)+1, sample-range part = tid>>6)
    const int   kk   = (tid & 63) + 1;
    const int   part = tid >> 6;
    const int   n0   = part * 256;
    const float fc   = f0[f] * (float)kk * (1.0f / 16000.0f); // cycles/sample

    // Rotation for stride-2 advance: z2 = exp(-2*pi*i * 2*fc)
    float p2 = fc + fc;
    p2 -= floorf(p2);
    float c2, s2;
    __sincosf(-TWO_PI_F * p2, &s2, &c2);
    const unsigned long long C2  = pk(c2, c2);
    const unsigned long long S2  = pk(s2, s2);
    const unsigned long long nS2 = pk(-s2, -s2);

    unsigned long long accRe = 0ull;  // (0.0f, 0.0f)
    unsigned long long accIm = 0ull;

    const float4* wv = (const float4*)(w + n0);

    #pragma unroll
    for (int blk = 0; blk < 4; ++blk) {
        // Seed both chains exactly: lane0 at sample nA (even), lane1 at nA+1 (odd)
        const int nA = n0 + blk * 64;
        float pA = fc * (float)nA;       pA -= floorf(pA);
        float pB = fc * (float)(nA + 1); pB -= floorf(pB);
        float sA, cA, sB, cB;
        __sincosf(-TWO_PI_F * pA, &sA, &cA);
        __sincosf(-TWO_PI_F * pB, &sB, &cB);
        unsigned long long RE = pk(cA, cB);
        unsigned long long IM = pk(sA, sB);

        #pragma unroll
        for (int j = 0; j < 16; ++j) {
            float4 wq = wv[blk * 16 + j];
            // samples (4j, 4j+1): accumulate then rotate by z2
            unsigned long long W1 = pk(wq.x, wq.y);
            accRe = fma2(W1, RE, accRe);
            accIm = fma2(W1, IM, accIm);
            unsigned long long tR  = mul2(RE, C2);
            unsigned long long tI  = mul2(IM, C2);
            unsigned long long RE2 = fma2(IM, nS2, tR);
            unsigned long long IM2 = fma2(RE, S2, tI);
            // samples (4j+2, 4j+3)
            unsigned long long W2 = pk(wq.z, wq.w);
            accRe = fma2(W2, RE2, accRe);
            accIm = fma2(W2, IM2, accIm);
            tR = mul2(RE2, C2);
            tI = mul2(IM2, C2);
            RE = fma2(IM2, nS2, tR);
            IM = fma2(RE2, S2, tI);
        }
    }

    float rLo, rHi, iLo, iHi;
    upk(accRe, rLo, rHi);
    upk(accIm, iLo, iHi);
    sRe[tid] = rLo + rHi;
    sIm[tid] = iLo + iHi;
    __syncthreads();

    if (tid < 64) {
        // combine the 4 sample-range partials for this harmonic
        float re = sRe[tid] + sRe[tid + 64] + sRe[tid + 128] + sRe[tid + 192];
        float im = sIm[tid] + sIm[tid + 64] + sIm[tid + 128] + sIm[tid + 192];
        float mag = sqrtf(re * re + im * im);
        if (fc > 0.5f) mag = 0.0f;  // Nyquist mask (tid<64 -> kk = tid+1)
        sRe[tid] = mag;

        // sum over harmonics: warp-reduce (warp0: k 1..32, warp1: k 33..64)
        float s = mag;
        #pragma unroll
        for (int o = 16; o > 0; o >>= 1)
            s += __shfl_xor_sync(0xffffffffu, s, o);
        if ((tid & 31) == 0) sAmp[tid >> 5] = s;
    }
    __syncthreads();

    if (tid < 64) {
        float amp = sAmp[0] + sAmp[1];
        out_hd[f * 64 + tid] = sRe[tid] / amp;
        if (tid == 0)
            out_amp[f] = fminf(fmaxf(amp * 2.0f, 0.0f), 1.0f);
    }
}

extern "C" void kernel_launch(void* const* d_in, const int* in_sizes, int n_in,
                              void* d_out, int out_size) {
    const float* audio = (const float*)d_in[0];
    const float* f0    = (const float*)d_in[1];
    const int frames   = in_sizes[1];  // 2*250*1 = 500
    float* out         = (float*)d_out;
    // output layout: [frames*64] harmonic_distribution, then [frames] amp
    morlet_kernel<<<frames, 256>>>(audio, f0, out, out + (size_t)frames * 64);
}

// round 2
// speedup vs baseline: 1.4031x; 1.4031x over previous
#include <cuda_runtime.h>
#include <cuda_bf16.h>

// MorletTransform via per-harmonic Goertzel recurrence.
// T[f,k] = sum_n  normalizer*gauss[n]*audio[f,n] * exp(-2*pi*i*fc*n),  fc = f0[f]*k/sr
// Goertzel: s_n = w_n + 2cos(th)*s_{n-1} - s_{n-2}, th = 2*pi*fc
//   segment [n0, n0+L): X_seg = e^{-i*th*(n0+L-1)} * (s_{L-1} - e^{-i*th} * s_{L-2})
// Two harmonics packed per thread in f32x2 lanes; windowed frame stored
// duplicated (w,w) in shared so no per-sample pack MOVs are needed.
// 256 threads = 32 harmonic-pairs x 8 segments of L=128.

#define TWO_PI_F 6.28318530717958647692f

__device__ __forceinline__ unsigned long long fma2(unsigned long long a,
                                                   unsigned long long b,
                                                   unsigned long long c) {
    unsigned long long d;
    asm("fma.rn.f32x2 %0, %1, %2, %3;" : "=l"(d) : "l"(a), "l"(b), "l"(c));
    return d;
}
__device__ __forceinline__ unsigned long long pk(float lo, float hi) {
    unsigned long long d;
    asm("mov.b64 %0, {%1, %2};" : "=l"(d) : "f"(lo), "f"(hi));
    return d;
}
__device__ __forceinline__ void upk(unsigned long long v, float& lo, float& hi) {
    asm("mov.b64 {%0, %1}, %2;" : "=f"(lo), "=f"(hi) : "l"(v));
}

__global__ void __launch_bounds__(256)
morlet_kernel(const float* __restrict__ audio,
              const float* __restrict__ f0,
              float* __restrict__ out_hd,
              float* __restrict__ out_amp) {
    const int f   = blockIdx.x;
    const int tid = threadIdx.x;

    __shared__ __align__(16) unsigned long long w2[1024]; // sample n -> (w[n], w[n])
    __shared__ float sRe[512];   // [seg][harmonic]
    __shared__ float sIm[512];
    __shared__ float sAmp[2];

    // normalizer = 1/sqrt(pi * tp), tp = sr/half_bw = 16000
    const float normalizer = rsqrtf(3.14159265358979f * 16000.0f);
    const float inv_tp     = 1.0f / 16000.0f;
    const float inv_sr     = 1.0f / 16000.0f;

    // --- windowed frame, stored duplicated for packed loads ---
    {
        float4 a = ((const float4*)audio)[(size_t)f * 256 + tid];
        int n = tid * 4;
        float v[4] = {a.x, a.y, a.z, a.w};
        unsigned long long o[4];
        #pragma unroll
        for (int i = 0; i < 4; ++i) {
            float d  = (float)(n + i - 512);
            float wv = v[i] * (normalizer * __expf(-d * d * inv_tp));
            o[i] = pk(wv, wv);
        }
        ((ulonglong2*)w2)[tid * 2]     = make_ulonglong2(o[0], o[1]);
        ((ulonglong2*)w2)[tid * 2 + 1] = make_ulonglong2(o[2], o[3]);
    }

    const float f0v  = f0[f];
    const int   pair = tid & 31;   // harmonic pair: k = 2*pair+1, 2*pair+2
    const int   seg  = tid >> 5;   // 8 segments of 128 samples
    const int   n0   = seg * 128;

    const float fcA = f0v * (float)(2 * pair + 1) * inv_sr;
    const float fcB = f0v * (float)(2 * pair + 2) * inv_sr;

    // Accurate sincos for the recurrence coefficient: cos error is amplified
    // by 1/sin(theta) (~51 at k=1,f0=50), so __sincosf is not safe here.
    float sthA, cthA, sthB, cthB;
    sincosf(TWO_PI_F * fcA, &sthA, &cthA);
    sincosf(TWO_PI_F * fcB, &sthB, &cthB);
    const unsigned long long C2   = pk(2.0f * cthA, 2.0f * cthB);
    const unsigned long long NEG1 = pk(-1.0f, -1.0f);

    __syncthreads();

    // --- Goertzel over this thread's 128-sample segment, both lanes ---
    unsigned long long s1 = 0ull, s2 = 0ull;
    const ulonglong2* wq = ((const ulonglong2*)w2) + (n0 >> 1); // idx m -> samples 2m,2m+1

    #pragma unroll 8
    for (int m = 0; m < 64; ++m) {
        ulonglong2 q = wq[m];                         // LDS.128, warp-broadcast
        unsigned long long t0 = fma2(NEG1, s2, q.x);  // w_{2m}   - s_{2m-2}
        unsigned long long s0 = fma2(C2, s1, t0);     // s_{2m}
        unsigned long long t1 = fma2(NEG1, s1, q.y);  // w_{2m+1} - s_{2m-1}
        unsigned long long sn = fma2(C2, s0, t1);     // s_{2m+1}
        s2 = s0;
        s1 = sn;
    }

    // --- finalize: X_seg rotated to global sample index ---
    float s1A, s1B, s2A, s2B;
    upk(s1, s1A, s1B);
    upk(s2, s2A, s2B);
    {
        float yre = fmaf(-cthA, s2A, s1A);
        float yim = sthA * s2A;
        float p   = fcA * (float)(n0 + 127);
        p -= floorf(p);
        float sphi, cphi;
        __sincosf(TWO_PI_F * p, &sphi, &cphi);
        sRe[seg * 64 + 2 * pair] = yre * cphi + yim * sphi;
        sIm[seg * 64 + 2 * pair] = yim * cphi - yre * sphi;
    }
    {
        float yre = fmaf(-cthB, s2B, s1B);
        float yim = sthB * s2B;
        float p   = fcB * (float)(n0 + 127);
        p -= floorf(p);
        float sphi, cphi;
        __sincosf(TWO_PI_F * p, &sphi, &cphi);
        sRe[seg * 64 + 2 * pair + 1] = yre * cphi + yim * sphi;
        sIm[seg * 64 + 2 * pair + 1] = yim * cphi - yre * sphi;
    }
    __syncthreads();

    // --- combine segments, magnitude, normalize ---
    if (tid < 64) {
        float re = 0.0f, im = 0.0f;
        #pragma unroll
        for (int s = 0; s < 8; ++s) {
            re += sRe[s * 64 + tid];
            im += sIm[s * 64 + tid];
        }
        float mag = sqrtf(re * re + im * im);
        float fch = f0v * (float)(tid + 1) * inv_sr;
        if (fch > 0.5f) mag = 0.0f;   // Nyquist mask
        sRe[tid] = mag;

        float s = mag;
        #pragma unroll
        for (int o = 16; o > 0; o >>= 1)
            s += __shfl_xor_sync(0xffffffffu, s, o);
        if ((tid & 31) == 0) sAmp[tid >> 5] = s;
    }
    __syncthreads();

    if (tid < 64) {
        float amp = sAmp[0] + sAmp[1];
        out_hd[f * 64 + tid] = sRe[tid] / amp;
        if (tid == 0)
            out_amp[f] = fminf(fmaxf(amp * 2.0f, 0.0f), 1.0f);
    }
}

extern "C" void kernel_launch(void* const* d_in, const int* in_sizes, int n_in,
                              void* d_out, int out_size) {
    const float* audio = (const float*)d_in[0];
    const float* f0    = (const float*)d_in[1];
    const int frames   = in_sizes[1];  // 2*250*1 = 500
    float* out         = (float*)d_out;
    morlet_kernel<<<frames, 256>>>(audio, f0, out, out + (size_t)frames * 64);
}

// round 3
// speedup vs baseline: 1.5220x; 1.0847x over previous
#include <cuda_runtime.h>
#include <cuda_bf16.h>

// MorletTransform via per-harmonic Goertzel recurrence.
// T[f,k] = sum_n normalizer*gauss[n]*audio[f,n] * exp(-2*pi*i*fc*n), fc=f0[f]*k/sr
// Goertzel: s_n = w_n + 2cos(th)*s_{n-1} - s_{n-2}, th = 2*pi*fc
//   segment [n0,n0+L): X = e^{-i*th*(n0+L-1)} * (s_{L-1} - e^{-i*th} s_{L-2})
// Mapping: 512 threads = 32 harmonic-pairs (f32x2 lanes) x 16 segments of 64.
// Accurate per-harmonic sincos computed ONCE by tid<64 into shared.

#define TWO_PI_F 6.28318530717958647692f

__device__ __forceinline__ unsigned long long fma2(unsigned long long a,
                                                   unsigned long long b,
                                                   unsigned long long c) {
    unsigned long long d;
    asm("fma.rn.f32x2 %0, %1, %2, %3;" : "=l"(d) : "l"(a), "l"(b), "l"(c));
    return d;
}
__device__ __forceinline__ unsigned long long pk(float lo, float hi) {
    unsigned long long d;
    asm("mov.b64 %0, {%1, %2};" : "=l"(d) : "f"(lo), "f"(hi));
    return d;
}
__device__ __forceinline__ void upk(unsigned long long v, float& lo, float& hi) {
    asm("mov.b64 {%0, %1}, %2;" : "=f"(lo), "=f"(hi) : "l"(v));
}

__global__ void __launch_bounds__(512, 4)
morlet_kernel(const float* __restrict__ audio,
              const float* __restrict__ f0,
              float* __restrict__ out_hd,
              float* __restrict__ out_amp) {
    const int f   = blockIdx.x;
    const int tid = threadIdx.x;

    __shared__ __align__(16) unsigned long long w2[1024]; // sample n -> (w[n], w[n])
    __shared__ __align__(8) float sCth[64];               // cos(theta_k)
    __shared__ __align__(8) float sSth[64];               // sin(theta_k)
    __shared__ float sRe[1024];                           // [seg][harmonic]
    __shared__ float sIm[1024];
    __shared__ float sAmp[2];

    // normalizer = 1/sqrt(pi * tp), tp = sr/half_bw = 16000
    const float normalizer = rsqrtf(3.14159265358979f * 16000.0f);
    const float inv_tp     = 1.0f / 16000.0f;
    const float inv_sr     = 1.0f / 16000.0f;
    const float f0v        = f0[f];

    // --- windowed frame (2 samples/thread), stored duplicated for packed loads ---
    {
        float2 a = ((const float2*)audio)[(size_t)f * 512 + tid];
        int n = tid * 2;
        float d0 = (float)(n - 512);
        float d1 = (float)(n + 1 - 512);
        float w0 = a.x * (normalizer * __expf(-d0 * d0 * inv_tp));
        float w1 = a.y * (normalizer * __expf(-d1 * d1 * inv_tp));
        ((ulonglong2*)w2)[tid] = make_ulonglong2(pk(w0, w0), pk(w1, w1));
    }

    // --- per-harmonic coefficients, once (accurate: cos error is amplified
    //     by 1/sin(theta) ~ 51 at k=1, so __sincosf is not safe here) ---
    if (tid < 64) {
        float fc = f0v * (float)(tid + 1) * inv_sr;
        float s, c;
        sincosf(TWO_PI_F * fc, &s, &c);
        sCth[tid] = c;
        sSth[tid] = s;
    }
    __syncthreads();

    const int pair = tid & 31;   // harmonics k = 2*pair+1, 2*pair+2
    const int seg  = tid >> 5;   // 16 segments of 64 samples
    const int n0   = seg * 64;

    float2 cth = ((const float2*)sCth)[pair];
    float2 sth = ((const float2*)sSth)[pair];
    const unsigned long long C2   = pk(2.0f * cth.x, 2.0f * cth.y);
    const unsigned long long NEG1 = pk(-1.0f, -1.0f);

    // --- Goertzel over this thread's 64-sample segment, both lanes ---
    unsigned long long s1 = 0ull, s2 = 0ull;
    const ulonglong2* wq = ((const ulonglong2*)w2) + seg * 32;

    #pragma unroll 8
    for (int m = 0; m < 32; ++m) {
        ulonglong2 q = wq[m];                         // LDS.128, warp-broadcast
        unsigned long long t0 = fma2(NEG1, s2, q.x);  // w - s_{n-2}
        unsigned long long s0 = fma2(C2, s1, t0);
        unsigned long long t1 = fma2(NEG1, s1, q.y);
        unsigned long long sn = fma2(C2, s0, t1);
        s2 = s0;
        s1 = sn;
    }

    // --- finalize: rotate segment result to global sample index ---
    float s1A, s1B, s2A, s2B;
    upk(s1, s1A, s1B);
    upk(s2, s2A, s2B);
    const float fcA = f0v * (float)(2 * pair + 1) * inv_sr;
    const float fcB = f0v * (float)(2 * pair + 2) * inv_sr;
    {
        float yre = fmaf(-cth.x, s2A, s1A);
        float yim = sth.x * s2A;
        float p   = fcA * (float)(n0 + 63);
        p -= floorf(p);
        float sphi, cphi;
        __sincosf(TWO_PI_F * p, &sphi, &cphi);
        sRe[seg * 64 + 2 * pair] = yre * cphi + yim * sphi;
        sIm[seg * 64 + 2 * pair] = yim * cphi - yre * sphi;
    }
    {
        float yre = fmaf(-cth.y, s2B, s1B);
        float yim = sth.y * s2B;
        float p   = fcB * (float)(n0 + 63);
        p -= floorf(p);
        float sphi, cphi;
        __sincosf(TWO_PI_F * p, &sphi, &cphi);
        sRe[seg * 64 + 2 * pair + 1] = yre * cphi + yim * sphi;
        sIm[seg * 64 + 2 * pair + 1] = yim * cphi - yre * sphi;
    }
    __syncthreads();

    // --- combine segments, magnitude, normalize ---
    if (tid < 64) {
        float re = 0.0f, im = 0.0f;
        #pragma unroll
        for (int s = 0; s < 16; ++s) {
            re += sRe[s * 64 + tid];
            im += sIm[s * 64 + tid];
        }
        float mag = sqrtf(re * re + im * im);
        float fch = f0v * (float)(tid + 1) * inv_sr;
        if (fch > 0.5f) mag = 0.0f;   // Nyquist mask
        sRe[tid] = mag;

        float s = mag;
        #pragma unroll
        for (int o = 16; o > 0; o >>= 1)
            s += __shfl_xor_sync(0xffffffffu, s, o);
        if ((tid & 31) == 0) sAmp[tid >> 5] = s;
    }
    __syncthreads();

    if (tid < 64) {
        float amp = sAmp[0] + sAmp[1];
        out_hd[f * 64 + tid] = sRe[tid] / amp;
        if (tid == 0)
            out_amp[f] = fminf(fmaxf(amp * 2.0f, 0.0f), 1.0f);
    }
}

extern "C" void kernel_launch(void* const* d_in, const int* in_sizes, int n_in,
                              void* d_out, int out_size) {
    const float* audio = (const float*)d_in[0];
    const float* f0    = (const float*)d_in[1];
    const int frames   = in_sizes[1];  // 2*250*1 = 500
    float* out         = (float*)d_out;
    morlet_kernel<<<frames, 512>>>(audio, f0, out, out + (size_t)frames * 64);
}